// round 9
// baseline (speedup 1.0000x reference)
#include <cuda_runtime.h>
#include <math.h>

#define NN 50000
#define EE 800000
#define TOT (EE + NN)

// ---------------- device scratch (no allocations allowed) ----------------
__device__ __align__(16) float g_h1[NN * 128];   // layer-1 linear output
__device__ __align__(16) float g_as1[NN * 4];    // per-node attn src terms (4 heads)
__device__ __align__(16) float g_ad1[NN * 4];    // per-node attn dst terms
__device__ __align__(16) float g_h2[NN * 2];     // layer-2 linear output
__device__ float g_as2[NN];
__device__ float g_ad2[NN];
__device__ int g_deg[NN];
__device__ int g_rowptr[NN + 1];
__device__ int g_cursor[NN];
__device__ int g_csr[TOT];

__device__ __forceinline__ float lrelu(float x) { return x > 0.f ? x : 0.2f * x; }

__device__ __forceinline__ unsigned long long ffma2(unsigned long long a,
                                                    unsigned long long b,
                                                    unsigned long long c) {
    unsigned long long d;
    asm("fma.rn.f32x2 %0, %1, %2, %3;" : "=l"(d) : "l"(a), "l"(b), "l"(c));
    return d;
}

// ---------------- CSR build ----------------
__global__ void k_zero_deg() {
    int i = blockIdx.x * blockDim.x + threadIdx.x;
    if (i < NN) g_deg[i] = 0;
}

__global__ void k_hist(const int* __restrict__ ei) {
    int i = blockIdx.x * blockDim.x + threadIdx.x;
    if (i < EE) {
        atomicAdd(&g_deg[ei[EE + i]], 1);      // dst of edge i
    } else if (i < TOT) {
        atomicAdd(&g_deg[i - EE], 1);          // self loop
    }
}

__global__ void k_scan() {
    __shared__ int part[1024];
    int t = threadIdx.x;
    const int C = (NN + 1023) / 1024;  // 49
    int lo = t * C;
    int hi = lo + C;
    if (hi > NN) hi = NN;
    int s = 0;
    for (int i = lo; i < hi; i++) s += g_deg[i];
    part[t] = s;
    __syncthreads();
    for (int off = 1; off < 1024; off <<= 1) {
        int v = (t >= off) ? part[t - off] : 0;
        __syncthreads();
        part[t] += v;
        __syncthreads();
    }
    int run = (t > 0) ? part[t - 1] : 0;
    for (int i = lo; i < hi; i++) {
        g_rowptr[i] = run;
        g_cursor[i] = run;
        run += g_deg[i];
    }
    if (t == 1023) g_rowptr[NN] = part[1023];
}

__global__ void k_scatter(const int* __restrict__ ei) {
    int i = blockIdx.x * blockDim.x + threadIdx.x;
    if (i < EE) {
        int src = ei[i];
        int dst = ei[EE + i];
        int pos = atomicAdd(&g_cursor[dst], 1);
        g_csr[pos] = src;
    } else if (i < TOT) {
        int v = i - EE;
        int pos = atomicAdd(&g_cursor[v], 1);
        g_csr[pos] = v;  // self loop
    }
}

// ---------------- GEMM1 + attn terms: h1 = x @ W1, as1/ad1 fused -----------
// Block: 64 rows x 128 cols; 256 threads; each thread 8 rows x 4 cols.
// K-dim packed in f32x2: acc holds (even-k partial, odd-k partial).
// smem: Ws2 = W interleaved pairs (k2,c) -> (W[2k2][c], W[2k2+1][c]) : 65536 B
//       xs  = x tile, 64 rows x 132-float stride                     : 33792 B
__global__ void __launch_bounds__(256) k_gemm1(const float* __restrict__ x,
                                               const float* __restrict__ W,
                                               const float* __restrict__ asrc,
                                               const float* __restrict__ adst) {
    extern __shared__ float sm[];
    float* Wsf = sm;                      // 16384 floats, interleaved layout
    float* xs = sm + 16384;               // 64 * 132 floats
    const unsigned long long* Ws2 = (const unsigned long long*)sm;
    int tid = threadIdx.x;
    int row0 = blockIdx.x * 64;

    // load W1 with even/odd-k interleave: float index (k2*128 + c)*2 + (k&1)
    const float4* W4 = (const float4*)W;
    for (int i = tid; i < 4096; i += 256) {
        float4 v = W4[i];
        int k = i >> 5, c = (i & 31) * 4;
        int b = (k >> 1) * 256 + (k & 1);
        Wsf[b + (c + 0) * 2] = v.x;
        Wsf[b + (c + 1) * 2] = v.y;
        Wsf[b + (c + 2) * 2] = v.z;
        Wsf[b + (c + 3) * 2] = v.w;
    }
    for (int i = tid; i < 2048; i += 256) {
        int r = i >> 5, c4 = i & 31;
        float4 v;
        if (row0 + r < NN) v = ((const float4*)x)[(row0 + r) * 32 + c4];
        else v = make_float4(0.f, 0.f, 0.f, 0.f);
        *(float4*)&xs[r * 132 + c4 * 4] = v;
    }
    __syncthreads();

    int tx = tid & 31, ty = tid >> 5;
    unsigned long long acc[8][4];
#pragma unroll
    for (int r = 0; r < 8; r++) { acc[r][0] = acc[r][1] = acc[r][2] = acc[r][3] = 0ull; }

    const float* xrow = &xs[ty * 8 * 132];
#pragma unroll 4
    for (int k2 = 0; k2 < 64; k2++) {
        ulonglong2 wA = *(const ulonglong2*)&Ws2[k2 * 128 + tx * 4];      // cols tx*4, tx*4+1
        ulonglong2 wB = *(const ulonglong2*)&Ws2[k2 * 128 + tx * 4 + 2];  // cols tx*4+2, +3
#pragma unroll
        for (int r = 0; r < 8; r++) {
            unsigned long long xv = *(const unsigned long long*)&xrow[r * 132 + 2 * k2];
            acc[r][0] = ffma2(xv, wA.x, acc[r][0]);
            acc[r][1] = ffma2(xv, wA.y, acc[r][1]);
            acc[r][2] = ffma2(xv, wB.x, acc[r][2]);
            acc[r][3] = ffma2(xv, wB.y, acc[r][3]);
        }
    }

    // epilogue: combine even/odd partials, store h1, fused attn terms
    float4 av = ((const float4*)asrc)[tx];
    float4 dv = ((const float4*)adst)[tx];
#pragma unroll
    for (int r = 0; r < 8; r++) {
        int row = row0 + ty * 8 + r;
        float2 p0 = *(float2*)&acc[r][0];
        float2 p1 = *(float2*)&acc[r][1];
        float2 p2 = *(float2*)&acc[r][2];
        float2 p3 = *(float2*)&acc[r][3];
        float v0 = p0.x + p0.y, v1 = p1.x + p1.y, v2 = p2.x + p2.y, v3 = p3.x + p3.y;
        if (row < NN)
            ((float4*)g_h1)[row * 32 + tx] = make_float4(v0, v1, v2, v3);
        float s = v0 * av.x + v1 * av.y + v2 * av.z + v3 * av.w;
        float d = v0 * dv.x + v1 * dv.y + v2 * dv.z + v3 * dv.w;
        s += __shfl_down_sync(0xffffffffu, s, 4);
        d += __shfl_down_sync(0xffffffffu, d, 4);
        s += __shfl_down_sync(0xffffffffu, s, 2);
        d += __shfl_down_sync(0xffffffffu, d, 2);
        s += __shfl_down_sync(0xffffffffu, s, 1);
        d += __shfl_down_sync(0xffffffffu, d, 1);
        if ((tx & 7) == 0 && row < NN) {
            g_as1[row * 4 + (tx >> 3)] = s;
            g_ad1[row * 4 + (tx >> 3)] = d;
        }
    }
}

// ---------------- layer-1 softmax agg + relu + layer-2 linear (warp/dst) ----
// h1o never touches memory: after computing the 128-ch aggregated+relu'd row
// in registers, immediately contract with W2 (128x2) and emit h2/as2/ad2.
__global__ void k_agg1(const float* __restrict__ b1,
                       const float* __restrict__ W2,
                       const float* __restrict__ asrc2,
                       const float* __restrict__ adst2) {
    int g = blockIdx.x * blockDim.x + threadIdx.x;
    int n = g >> 5, lane = g & 31;
    if (n >= NN) return;
    int beg = g_rowptr[n], end = g_rowptr[n + 1];
    float4 ad = *(const float4*)&g_ad1[n * 4];

    // pass 1: per-head max over incoming edges (lanes stride over edges)
    float m0 = -1e30f, m1 = -1e30f, m2 = -1e30f, m3 = -1e30f;
    for (int j = beg + lane; j < end; j += 32) {
        int s = g_csr[j];
        float4 avv = *(const float4*)&g_as1[s * 4];
        m0 = fmaxf(m0, lrelu(avv.x + ad.x));
        m1 = fmaxf(m1, lrelu(avv.y + ad.y));
        m2 = fmaxf(m2, lrelu(avv.z + ad.z));
        m3 = fmaxf(m3, lrelu(avv.w + ad.w));
    }
#pragma unroll
    for (int off = 16; off; off >>= 1) {
        m0 = fmaxf(m0, __shfl_xor_sync(0xffffffffu, m0, off));
        m1 = fmaxf(m1, __shfl_xor_sync(0xffffffffu, m1, off));
        m2 = fmaxf(m2, __shfl_xor_sync(0xffffffffu, m2, off));
        m3 = fmaxf(m3, __shfl_xor_sync(0xffffffffu, m3, off));
    }

    // pass 2: lanes map channels; iterate edges serially, accumulate p and p*h
    float a0 = 0.f, a1 = 0.f, a2 = 0.f, a3 = 0.f;
    float d0 = 0.f, d1 = 0.f, d2 = 0.f, d3 = 0.f;
    for (int j = beg; j < end; j++) {
        int s = g_csr[j];                            // uniform across warp -> broadcast
        float4 avv = *(const float4*)&g_as1[s * 4];  // uniform -> broadcast
        float p0 = __expf(lrelu(avv.x + ad.x) - m0);
        float p1 = __expf(lrelu(avv.y + ad.y) - m1);
        float p2 = __expf(lrelu(avv.z + ad.z) - m2);
        float p3 = __expf(lrelu(avv.w + ad.w) - m3);
        const float* hr = &g_h1[s * 128];
        a0 = fmaf(p0, hr[lane], a0);
        a1 = fmaf(p1, hr[32 + lane], a1);
        a2 = fmaf(p2, hr[64 + lane], a2);
        a3 = fmaf(p3, hr[96 + lane], a3);
        d0 += p0; d1 += p1; d2 += p2; d3 += p3;
    }
    float o0 = fmaxf(a0 / (d0 + 1e-16f) + __ldg(&b1[lane]), 0.f);
    float o1 = fmaxf(a1 / (d1 + 1e-16f) + __ldg(&b1[32 + lane]), 0.f);
    float o2 = fmaxf(a2 / (d2 + 1e-16f) + __ldg(&b1[64 + lane]), 0.f);
    float o3 = fmaxf(a3 / (d3 + 1e-16f) + __ldg(&b1[96 + lane]), 0.f);

    // fused layer-2 linear: c = o @ W2  (W2 is [128,2] row-major)
    float c0 = o0 * __ldg(&W2[lane * 2])            + o1 * __ldg(&W2[(32 + lane) * 2])
             + o2 * __ldg(&W2[(64 + lane) * 2])     + o3 * __ldg(&W2[(96 + lane) * 2]);
    float c1 = o0 * __ldg(&W2[lane * 2 + 1])        + o1 * __ldg(&W2[(32 + lane) * 2 + 1])
             + o2 * __ldg(&W2[(64 + lane) * 2 + 1]) + o3 * __ldg(&W2[(96 + lane) * 2 + 1]);
#pragma unroll
    for (int off = 16; off; off >>= 1) {
        c0 += __shfl_xor_sync(0xffffffffu, c0, off);
        c1 += __shfl_xor_sync(0xffffffffu, c1, off);
    }
    if (lane == 0) {
        g_h2[2 * n]     = c0;
        g_h2[2 * n + 1] = c1;
        g_as2[n] = c0 * __ldg(&asrc2[0]) + c1 * __ldg(&asrc2[1]);
        g_ad2[n] = c0 * __ldg(&adst2[0]) + c1 * __ldg(&adst2[1]);
    }
}

// ---------------- layer-2 aggregation + log_softmax (warp per dst) ----------
__global__ void k_agg2(const float* __restrict__ b2, float* __restrict__ out) {
    int g = blockIdx.x * blockDim.x + threadIdx.x;
    int n = g >> 5, lane = g & 31;
    if (n >= NN) return;
    int beg = g_rowptr[n], end = g_rowptr[n + 1];
    float adv = g_ad2[n];

    float m = -1e30f;
    for (int j = beg + lane; j < end; j += 32)
        m = fmaxf(m, lrelu(g_as2[g_csr[j]] + adv));
#pragma unroll
    for (int off = 16; off; off >>= 1)
        m = fmaxf(m, __shfl_xor_sync(0xffffffffu, m, off));

    float a0 = 0.f, a1 = 0.f, den = 0.f;
    for (int j = beg + lane; j < end; j += 32) {
        int s = g_csr[j];
        float p = __expf(lrelu(g_as2[s] + adv) - m);
        float2 hv = *(const float2*)&g_h2[2 * s];
        a0 = fmaf(p, hv.x, a0);
        a1 = fmaf(p, hv.y, a1);
        den += p;
    }
#pragma unroll
    for (int off = 16; off; off >>= 1) {
        a0 += __shfl_xor_sync(0xffffffffu, a0, off);
        a1 += __shfl_xor_sync(0xffffffffu, a1, off);
        den += __shfl_xor_sync(0xffffffffu, den, off);
    }
    if (lane == 0) {
        float o0 = a0 / (den + 1e-16f) + b2[0];
        float o1 = a1 / (den + 1e-16f) + b2[1];
        float mm = fmaxf(o0, o1);
        float lse = mm + logf(expf(o0 - mm) + expf(o1 - mm));
        out[2 * n]     = o0 - lse;
        out[2 * n + 1] = o1 - lse;
    }
}

// ---------------- launch ----------------
extern "C" void kernel_launch(void* const* d_in, const int* in_sizes, int n_in,
                              void* d_out, int out_size) {
    (void)in_sizes; (void)n_in; (void)out_size;
    const float* x     = (const float*)d_in[0];
    const int*   ei    = (const int*)d_in[1];   // [2, E]: first E = src, next E = dst
    const float* W1    = (const float*)d_in[2];
    const float* asrc1 = (const float*)d_in[3];
    const float* adst1 = (const float*)d_in[4];
    const float* b1    = (const float*)d_in[5];
    const float* W2    = (const float*)d_in[6];
    const float* asrc2 = (const float*)d_in[7];
    const float* adst2 = (const float*)d_in[8];
    const float* b2    = (const float*)d_in[9];
    float* out = (float*)d_out;

    cudaFuncSetAttribute(k_gemm1, cudaFuncAttributeMaxDynamicSharedMemorySize, 99328);

    // CSR build (int atomics only; same graph used by both layers)
    k_zero_deg<<<(NN + 255) / 256, 256>>>();
    k_hist<<<(TOT + 255) / 256, 256>>>(ei);
    k_scan<<<1, 1024>>>();
    k_scatter<<<(TOT + 255) / 256, 256>>>(ei);

    // layer 1 (linear + attn terms fused)
    k_gemm1<<<(NN + 63) / 64, 256, 99328>>>(x, W1, asrc1, adst1);
    // layer-1 softmax agg + relu + layer-2 linear fused
    k_agg1<<<(NN * 32 + 255) / 256, 256>>>(b1, W2, asrc2, adst2);
    // layer-2 aggregation + log_softmax
    k_agg2<<<(NN * 32 + 255) / 256, 256>>>(b2, out);
}

// round 10
// speedup vs baseline: 1.6178x; 1.6178x over previous
#include <cuda_runtime.h>
#include <math.h>

#define NN 50000
#define EE 800000
#define TOT (EE + NN)

// ---------------- device scratch (no allocations allowed) ----------------
__device__ __align__(16) float g_h1[NN * 128];   // layer-1 linear output
__device__ __align__(16) float g_as1[NN * 4];    // per-node attn src terms (4 heads)
__device__ __align__(16) float g_ad1[NN * 4];    // per-node attn dst terms
__device__ __align__(16) float g_h2[NN * 2];     // layer-2 linear output
__device__ float g_as2[NN];
__device__ float g_ad2[NN];
__device__ int g_deg[NN];
__device__ int g_rowptr[NN + 1];
__device__ int g_cursor[NN];
__device__ int g_csr[TOT];

__device__ __forceinline__ float lrelu(float x) { return x > 0.f ? x : 0.2f * x; }

// ---------------- CSR build ----------------
__global__ void k_zero_deg() {
    int i = blockIdx.x * blockDim.x + threadIdx.x;
    if (i < NN) g_deg[i] = 0;
}

__global__ void k_hist(const int* __restrict__ ei) {
    int i = blockIdx.x * blockDim.x + threadIdx.x;
    if (i < EE) {
        atomicAdd(&g_deg[ei[EE + i]], 1);      // dst of edge i
    } else if (i < TOT) {
        atomicAdd(&g_deg[i - EE], 1);          // self loop
    }
}

__global__ void k_scan() {
    __shared__ int part[1024];
    int t = threadIdx.x;
    const int C = (NN + 1023) / 1024;  // 49
    int lo = t * C;
    int hi = lo + C;
    if (hi > NN) hi = NN;
    int s = 0;
    for (int i = lo; i < hi; i++) s += g_deg[i];
    part[t] = s;
    __syncthreads();
    for (int off = 1; off < 1024; off <<= 1) {
        int v = (t >= off) ? part[t - off] : 0;
        __syncthreads();
        part[t] += v;
        __syncthreads();
    }
    int run = (t > 0) ? part[t - 1] : 0;
    for (int i = lo; i < hi; i++) {
        g_rowptr[i] = run;
        g_cursor[i] = run;
        run += g_deg[i];
    }
    if (t == 1023) g_rowptr[NN] = part[1023];
}

__global__ void k_scatter(const int* __restrict__ ei) {
    int i = blockIdx.x * blockDim.x + threadIdx.x;
    if (i < EE) {
        int src = ei[i];
        int dst = ei[EE + i];
        int pos = atomicAdd(&g_cursor[dst], 1);
        g_csr[pos] = src;
    } else if (i < TOT) {
        int v = i - EE;
        int pos = atomicAdd(&g_cursor[v], 1);
        g_csr[pos] = v;  // self loop
    }
}

// ---------------- GEMM1 + attn terms: h1 = x @ W1, as1/ad1 fused -----------
// PROVEN scalar-FFMA mainloop (measured ~110us inside the 277us run).
// Block: 64 rows x 128 cols; 256 threads; each thread 8 rows x 4 cols.
// Whole W1 (64KB) + padded x-tile (33KB) in dynamic smem.
// Epilogue additionally computes per-node attention terms from the
// register-resident accumulators (kills the separate k_attn1 kernel).
__global__ void __launch_bounds__(256) k_gemm1(const float* __restrict__ x,
                                               const float* __restrict__ W,
                                               const float* __restrict__ asrc,
                                               const float* __restrict__ adst) {
    extern __shared__ float sm[];
    float* Ws = sm;            // 16384 floats
    float* xs = sm + 16384;    // 64 * 132 floats (padded stride kills bank conflicts)
    int tid = threadIdx.x;
    int row0 = blockIdx.x * 64;

    const float4* W4 = (const float4*)W;
    float4* Ws4 = (float4*)Ws;
    for (int i = tid; i < 4096; i += 256) Ws4[i] = W4[i];
    for (int i = tid; i < 2048; i += 256) {
        int r = i >> 5, c4 = i & 31;
        float4 v;
        if (row0 + r < NN) v = ((const float4*)x)[(row0 + r) * 32 + c4];
        else v = make_float4(0.f, 0.f, 0.f, 0.f);
        *(float4*)&xs[r * 132 + c4 * 4] = v;
    }
    __syncthreads();

    int tx = tid & 31, ty = tid >> 5;
    float acc[8][4];
#pragma unroll
    for (int r = 0; r < 8; r++) { acc[r][0] = acc[r][1] = acc[r][2] = acc[r][3] = 0.f; }

    const float4* Wv = (const float4*)Ws;
#pragma unroll 8
    for (int k = 0; k < 128; k++) {
        float4 w = Wv[k * 32 + tx];
#pragma unroll
        for (int r = 0; r < 8; r++) {
            float xv = xs[(ty * 8 + r) * 132 + k];
            acc[r][0] = fmaf(xv, w.x, acc[r][0]);
            acc[r][1] = fmaf(xv, w.y, acc[r][1]);
            acc[r][2] = fmaf(xv, w.z, acc[r][2]);
            acc[r][3] = fmaf(xv, w.w, acc[r][3]);
        }
    }

    // epilogue: store h1 + fused attention terms (as1/ad1)
    float4 av = ((const float4*)asrc)[tx];
    float4 dv = ((const float4*)adst)[tx];
#pragma unroll
    for (int r = 0; r < 8; r++) {
        int row = row0 + ty * 8 + r;
        if (row < NN)
            ((float4*)g_h1)[row * 32 + tx] =
                make_float4(acc[r][0], acc[r][1], acc[r][2], acc[r][3]);
        float s = acc[r][0] * av.x + acc[r][1] * av.y + acc[r][2] * av.z + acc[r][3] * av.w;
        float d = acc[r][0] * dv.x + acc[r][1] * dv.y + acc[r][2] * dv.z + acc[r][3] * dv.w;
        s += __shfl_down_sync(0xffffffffu, s, 4);
        d += __shfl_down_sync(0xffffffffu, d, 4);
        s += __shfl_down_sync(0xffffffffu, s, 2);
        d += __shfl_down_sync(0xffffffffu, d, 2);
        s += __shfl_down_sync(0xffffffffu, s, 1);
        d += __shfl_down_sync(0xffffffffu, d, 1);
        if ((tx & 7) == 0 && row < NN) {
            g_as1[row * 4 + (tx >> 3)] = s;
            g_ad1[row * 4 + (tx >> 3)] = d;
        }
    }
}

// ---------------- layer-1 softmax agg + relu + layer-2 linear (warp/dst) ----
// h1o never touches memory: after computing the 128-ch aggregated+relu'd row
// in registers, immediately contract with W2 (128x2) and emit h2/as2/ad2.
__global__ void k_agg1(const float* __restrict__ b1,
                       const float* __restrict__ W2,
                       const float* __restrict__ asrc2,
                       const float* __restrict__ adst2) {
    int g = blockIdx.x * blockDim.x + threadIdx.x;
    int n = g >> 5, lane = g & 31;
    if (n >= NN) return;
    int beg = g_rowptr[n], end = g_rowptr[n + 1];
    float4 ad = *(const float4*)&g_ad1[n * 4];

    // pass 1: per-head max over incoming edges (lanes stride over edges)
    float m0 = -1e30f, m1 = -1e30f, m2 = -1e30f, m3 = -1e30f;
    for (int j = beg + lane; j < end; j += 32) {
        int s = g_csr[j];
        float4 avv = *(const float4*)&g_as1[s * 4];
        m0 = fmaxf(m0, lrelu(avv.x + ad.x));
        m1 = fmaxf(m1, lrelu(avv.y + ad.y));
        m2 = fmaxf(m2, lrelu(avv.z + ad.z));
        m3 = fmaxf(m3, lrelu(avv.w + ad.w));
    }
#pragma unroll
    for (int off = 16; off; off >>= 1) {
        m0 = fmaxf(m0, __shfl_xor_sync(0xffffffffu, m0, off));
        m1 = fmaxf(m1, __shfl_xor_sync(0xffffffffu, m1, off));
        m2 = fmaxf(m2, __shfl_xor_sync(0xffffffffu, m2, off));
        m3 = fmaxf(m3, __shfl_xor_sync(0xffffffffu, m3, off));
    }

    // pass 2: lanes map channels; iterate edges serially, accumulate p and p*h
    float a0 = 0.f, a1 = 0.f, a2 = 0.f, a3 = 0.f;
    float d0 = 0.f, d1 = 0.f, d2 = 0.f, d3 = 0.f;
    for (int j = beg; j < end; j++) {
        int s = g_csr[j];                            // uniform across warp -> broadcast
        float4 avv = *(const float4*)&g_as1[s * 4];  // uniform -> broadcast
        float p0 = __expf(lrelu(avv.x + ad.x) - m0);
        float p1 = __expf(lrelu(avv.y + ad.y) - m1);
        float p2 = __expf(lrelu(avv.z + ad.z) - m2);
        float p3 = __expf(lrelu(avv.w + ad.w) - m3);
        const float* hr = &g_h1[s * 128];
        a0 = fmaf(p0, hr[lane], a0);
        a1 = fmaf(p1, hr[32 + lane], a1);
        a2 = fmaf(p2, hr[64 + lane], a2);
        a3 = fmaf(p3, hr[96 + lane], a3);
        d0 += p0; d1 += p1; d2 += p2; d3 += p3;
    }
    float o0 = fmaxf(a0 / (d0 + 1e-16f) + __ldg(&b1[lane]), 0.f);
    float o1 = fmaxf(a1 / (d1 + 1e-16f) + __ldg(&b1[32 + lane]), 0.f);
    float o2 = fmaxf(a2 / (d2 + 1e-16f) + __ldg(&b1[64 + lane]), 0.f);
    float o3 = fmaxf(a3 / (d3 + 1e-16f) + __ldg(&b1[96 + lane]), 0.f);

    // fused layer-2 linear: c = o @ W2  (W2 is [128,2] row-major)
    float c0 = o0 * __ldg(&W2[lane * 2])            + o1 * __ldg(&W2[(32 + lane) * 2])
             + o2 * __ldg(&W2[(64 + lane) * 2])     + o3 * __ldg(&W2[(96 + lane) * 2]);
    float c1 = o0 * __ldg(&W2[lane * 2 + 1])        + o1 * __ldg(&W2[(32 + lane) * 2 + 1])
             + o2 * __ldg(&W2[(64 + lane) * 2 + 1]) + o3 * __ldg(&W2[(96 + lane) * 2 + 1]);
#pragma unroll
    for (int off = 16; off; off >>= 1) {
        c0 += __shfl_xor_sync(0xffffffffu, c0, off);
        c1 += __shfl_xor_sync(0xffffffffu, c1, off);
    }
    if (lane == 0) {
        g_h2[2 * n]     = c0;
        g_h2[2 * n + 1] = c1;
        g_as2[n] = c0 * __ldg(&asrc2[0]) + c1 * __ldg(&asrc2[1]);
        g_ad2[n] = c0 * __ldg(&adst2[0]) + c1 * __ldg(&adst2[1]);
    }
}

// ---------------- layer-2 aggregation + log_softmax (warp per dst) ----------
__global__ void k_agg2(const float* __restrict__ b2, float* __restrict__ out) {
    int g = blockIdx.x * blockDim.x + threadIdx.x;
    int n = g >> 5, lane = g & 31;
    if (n >= NN) return;
    int beg = g_rowptr[n], end = g_rowptr[n + 1];
    float adv = g_ad2[n];

    float m = -1e30f;
    for (int j = beg + lane; j < end; j += 32)
        m = fmaxf(m, lrelu(g_as2[g_csr[j]] + adv));
#pragma unroll
    for (int off = 16; off; off >>= 1)
        m = fmaxf(m, __shfl_xor_sync(0xffffffffu, m, off));

    float a0 = 0.f, a1 = 0.f, den = 0.f;
    for (int j = beg + lane; j < end; j += 32) {
        int s = g_csr[j];
        float p = __expf(lrelu(g_as2[s] + adv) - m);
        float2 hv = *(const float2*)&g_h2[2 * s];
        a0 = fmaf(p, hv.x, a0);
        a1 = fmaf(p, hv.y, a1);
        den += p;
    }
#pragma unroll
    for (int off = 16; off; off >>= 1) {
        a0 += __shfl_xor_sync(0xffffffffu, a0, off);
        a1 += __shfl_xor_sync(0xffffffffu, a1, off);
        den += __shfl_xor_sync(0xffffffffu, den, off);
    }
    if (lane == 0) {
        float o0 = a0 / (den + 1e-16f) + b2[0];
        float o1 = a1 / (den + 1e-16f) + b2[1];
        float mm = fmaxf(o0, o1);
        float lse = mm + logf(expf(o0 - mm) + expf(o1 - mm));
        out[2 * n]     = o0 - lse;
        out[2 * n + 1] = o1 - lse;
    }
}

// ---------------- launch ----------------
extern "C" void kernel_launch(void* const* d_in, const int* in_sizes, int n_in,
                              void* d_out, int out_size) {
    (void)in_sizes; (void)n_in; (void)out_size;
    const float* x     = (const float*)d_in[0];
    const int*   ei    = (const int*)d_in[1];   // [2, E]: first E = src, next E = dst
    const float* W1    = (const float*)d_in[2];
    const float* asrc1 = (const float*)d_in[3];
    const float* adst1 = (const float*)d_in[4];
    const float* b1    = (const float*)d_in[5];
    const float* W2    = (const float*)d_in[6];
    const float* asrc2 = (const float*)d_in[7];
    const float* adst2 = (const float*)d_in[8];
    const float* b2    = (const float*)d_in[9];
    float* out = (float*)d_out;

    cudaFuncSetAttribute(k_gemm1, cudaFuncAttributeMaxDynamicSharedMemorySize, 99328);

    // CSR build (int atomics only; same graph used by both layers)
    k_zero_deg<<<(NN + 255) / 256, 256>>>();
    k_hist<<<(TOT + 255) / 256, 256>>>(ei);
    k_scan<<<1, 1024>>>();
    k_scatter<<<(TOT + 255) / 256, 256>>>(ei);

    // layer 1 (linear + attn terms fused into GEMM epilogue)
    k_gemm1<<<(NN + 63) / 64, 256, 99328>>>(x, W1, asrc1, adst1);
    // layer-1 softmax agg + relu + layer-2 linear fused
    k_agg1<<<(NN * 32 + 255) / 256, 256>>>(b1, W2, asrc2, adst2);
    // layer-2 aggregation + log_softmax
    k_agg2<<<(NN * 32 + 255) / 256, 256>>>(b2, out);
}